// round 12
// baseline (speedup 1.0000x reference)
#include <cuda_runtime.h>

// out[b,i,j] = W[b,i,j] - (dot(W[b,i,:], x[b,:]) + ETA*gL[b,i]) * x[b,j]
// B=64, D=1024, fp32. Purely HBM-bound: 256MB read + 256MB write.
// One warp per row; W row held in registers across dot + update (single read of W).
// x[b] staged in shared memory once per block (8 rows share it).
// R12: x kept ONLY in smem (re-read in update loop) to halve data registers
// (64->32), targeting real 4 CTAs/SM occupancy for deeper HBM queues.

#define B_DIM 64
#define D_DIM 1024
#define ETA 0.01f
#define ROWS_PER_BLOCK 8           // 8 warps * 1 row each
#define THREADS 256
#define F4_PER_LANE 8              // 1024 floats / 32 lanes / 4 per float4

__global__ __launch_bounds__(THREADS, 4)
void ttt_update_kernel(const float* __restrict__ W,
                       const float* __restrict__ x,
                       const float* __restrict__ gL,
                       float* __restrict__ out)
{
    __shared__ float4 xs[D_DIM / 4];   // 4 KB: x[b] staged once per block

    const int groups_per_batch = D_DIM / ROWS_PER_BLOCK;   // 128
    const int b  = blockIdx.x / groups_per_batch;
    const int rg = blockIdx.x % groups_per_batch;

    // Stage x[b] into shared memory (256 threads x float4 = 1024 floats).
    xs[threadIdx.x] =
        reinterpret_cast<const float4*>(x + (size_t)b * D_DIM)[threadIdx.x];

    const int warp = threadIdx.x >> 5;
    const int lane = threadIdx.x & 31;
    const int row  = rg * ROWS_PER_BLOCK + warp;

    const size_t row_off = ((size_t)b * D_DIM + row) * D_DIM;
    const float4* __restrict__ wrow = reinterpret_cast<const float4*>(W + row_off);
    float4* __restrict__       orow = reinterpret_cast<float4*>(out + row_off);

    // Pure front batch of 8 independent LDG.128s, streaming (W touched once).
    float4 wv[F4_PER_LANE];
#pragma unroll
    for (int k = 0; k < F4_PER_LANE; k++)
        wv[k] = __ldcs(wrow + lane + k * 32);
    const float g = __ldg(gL + (size_t)b * D_DIM + row);

    __syncthreads();   // xs ready (overlapped with LDG latency)

    // Row dot product — x read straight from smem, no register copy.
    float acc = 0.0f;
#pragma unroll
    for (int k = 0; k < F4_PER_LANE; k++) {
        const float4 xv = xs[lane + k * 32];
        acc += wv[k].x * xv.x;
        acc += wv[k].y * xv.y;
        acc += wv[k].z * xv.z;
        acc += wv[k].w * xv.w;
    }
    // Warp-wide reduce (no smem, no bar)
#pragma unroll
    for (int off = 16; off > 0; off >>= 1)
        acc += __shfl_xor_sync(0xffffffffu, acc, off);

    const float coeff = acc + ETA * g;

    // Update + streaming store; x re-read from smem (conflict-free, cheap).
#pragma unroll
    for (int k = 0; k < F4_PER_LANE; k++) {
        const float4 xv = xs[lane + k * 32];
        float4 o;
        o.x = wv[k].x - coeff * xv.x;
        o.y = wv[k].y - coeff * xv.y;
        o.z = wv[k].z - coeff * xv.z;
        o.w = wv[k].w - coeff * xv.w;
        __stcs(orow + lane + k * 32, o);
    }
}

extern "C" void kernel_launch(void* const* d_in, const int* in_sizes, int n_in,
                              void* d_out, int out_size)
{
    const float* W  = (const float*)d_in[0];   // [B, D, D]
    const float* x  = (const float*)d_in[1];   // [B, D, 1]
    const float* gL = (const float*)d_in[2];   // [B, D, 1]
    float* out = (float*)d_out;                // [B, D, D]

    const int grid = B_DIM * (D_DIM / ROWS_PER_BLOCK);   // 64 * 128 = 8192
    ttt_update_kernel<<<grid, THREADS>>>(W, x, gL, out);
}

// round 13
// speedup vs baseline: 1.2357x; 1.2357x over previous
#include <cuda_runtime.h>

// out[b,i,j] = W[b,i,j] - (dot(W[b,i,:], x[b,:]) + ETA*gL[b,i]) * x[b,j]
// B=64, D=1024, fp32. Purely HBM-bound: 256MB read + 256MB write.
// One warp per row; W row held in registers across dot + update (single read of W).
// x[b] staged in shared memory once per block (8 rows share it).
// R13: revert to R6 structure (regs=78, 2 CTAs/SM — the proven 82.0us config;
// R12 proved occupancy is NOT the limiter). Single delta: a CTA-wide barrier
// between read/compute and store phases, so each CTA presents a 32KB read
// burst then a 32KB write burst to the memory controller (coarser R/W
// granularity -> fewer DRAM bus turnarounds).

#define B_DIM 64
#define D_DIM 1024
#define ETA 0.01f
#define ROWS_PER_BLOCK 8           // 8 warps * 1 row each
#define THREADS 256
#define F4_PER_LANE 8              // 1024 floats / 32 lanes / 4 per float4

__global__ __launch_bounds__(THREADS, 2)
void ttt_update_kernel(const float* __restrict__ W,
                       const float* __restrict__ x,
                       const float* __restrict__ gL,
                       float* __restrict__ out)
{
    __shared__ float4 xs[D_DIM / 4];   // 4 KB: x[b] staged once per block

    const int groups_per_batch = D_DIM / ROWS_PER_BLOCK;   // 128
    const int b  = blockIdx.x / groups_per_batch;
    const int rg = blockIdx.x % groups_per_batch;

    // Stage x[b] into shared memory (256 threads x float4 = 1024 floats)
    xs[threadIdx.x] =
        reinterpret_cast<const float4*>(x + (size_t)b * D_DIM)[threadIdx.x];

    const int warp = threadIdx.x >> 5;
    const int lane = threadIdx.x & 31;
    const int row  = rg * ROWS_PER_BLOCK + warp;

    const size_t row_off = ((size_t)b * D_DIM + row) * D_DIM;
    const float4* __restrict__ wrow = reinterpret_cast<const float4*>(W + row_off);
    float4* __restrict__       orow = reinterpret_cast<float4*>(out + row_off);

    // Pure front batch of 8 independent LDG.128s (max MLP before any
    // dependent work); the gL scalar load rides along too.
    float4 wv[F4_PER_LANE];
#pragma unroll
    for (int k = 0; k < F4_PER_LANE; k++)
        wv[k] = wrow[lane + k * 32];
    const float g = gL[(size_t)b * D_DIM + row];

    __syncthreads();   // xs ready (overlapped with LDG latency)

    float4 xv[F4_PER_LANE];
#pragma unroll
    for (int k = 0; k < F4_PER_LANE; k++)
        xv[k] = xs[lane + k * 32];

    // Row dot product
    float acc = 0.0f;
#pragma unroll
    for (int k = 0; k < F4_PER_LANE; k++) {
        acc += wv[k].x * xv[k].x;
        acc += wv[k].y * xv[k].y;
        acc += wv[k].z * xv[k].z;
        acc += wv[k].w * xv[k].w;
    }
    // Warp-wide reduce (no smem, no bar)
#pragma unroll
    for (int off = 16; off > 0; off >>= 1)
        acc += __shfl_xor_sync(0xffffffffu, acc, off);

    const float coeff = acc + ETA * g;

    // Align all warps of the CTA before the write burst: reads done, then
    // the whole CTA streams 32KB of stores together.
    __syncthreads();

    // Update + store, straight from registers
#pragma unroll
    for (int k = 0; k < F4_PER_LANE; k++) {
        float4 o;
        o.x = wv[k].x - coeff * xv[k].x;
        o.y = wv[k].y - coeff * xv[k].y;
        o.z = wv[k].z - coeff * xv[k].z;
        o.w = wv[k].w - coeff * xv[k].w;
        orow[lane + k * 32] = o;
    }
}

extern "C" void kernel_launch(void* const* d_in, const int* in_sizes, int n_in,
                              void* d_out, int out_size)
{
    const float* W  = (const float*)d_in[0];   // [B, D, D]
    const float* x  = (const float*)d_in[1];   // [B, D, 1]
    const float* gL = (const float*)d_in[2];   // [B, D, 1]
    float* out = (float*)d_out;                // [B, D, D]

    const int grid = B_DIM * (D_DIM / ROWS_PER_BLOCK);   // 64 * 128 = 8192
    ttt_update_kernel<<<grid, THREADS>>>(W, x, gL, out);
}